// round 2
// baseline (speedup 1.0000x reference)
#include <cuda_runtime.h>
#include <math.h>

#define Bn 256
#define Sn 256
#define Tn 32
#define Hn 512
#define En 128
#define EDn 32
#define An 8
#define NTn 80

// Persistent scratch (no allocations allowed)
__device__ float g_h[2][Bn*Hn];          // double-buffered hidden state
__device__ float g_c[Bn*Hn];             // cell state
__device__ float g_enc_out[Sn*Bn*Hn];    // (S,B,H) encoder outputs, 134 MB
__device__ float g_enc_score[Sn*Bn];     // (S,B) attention logits (enc part)
__device__ int   g_inp[Bn*2];            // decoder feedback tokens

__device__ __forceinline__ float sigmoidf_(float x){ return 1.f/(1.f+expf(-x)); }

__global__ void init_k(){
    int i = blockIdx.x*blockDim.x + threadIdx.x;
    if (i < Bn*Hn){ g_h[0][i]=0.f; g_h[1][i]=0.f; g_c[i]=0.f; }
    if (i < Bn*2) g_inp[i]=0;
}

// ---------------------------------------------------------------------------
// Fused LSTM step: z = [x_t, h] @ W^T + b ; gates ; c,h update.
// Block computes a 32(batch) x 32(h-units) tile = 32x128 gate values, K = K1+H.
// Grid: 8 (batch tiles) x 16 (h tiles) = 128 blocks, 256 threads.
// ---------------------------------------------------------------------------
template<int K1, bool ENC>
__global__ __launch_bounds__(256) void lstm_k(
    const float* __restrict__ Wi, const float* __restrict__ Wh,
    const float* __restrict__ bias,
    const int*   __restrict__ enc_input, const float* __restrict__ enc_embed,
    const float* __restrict__ act_emb,   const float* __restrict__ tgt_emb,
    int t, int par)
{
    constexpr int KT  = K1 + Hn;
    constexpr int NKT = KT/16;
    __shared__ float As[16][34];     // [kk][row], padded
    __shared__ float Bs[16][136];    // [kk][col], padded (col = g*32+j local)
    __shared__ float zs[32*128];

    const int tid = threadIdx.x;
    const int b0  = (blockIdx.x & 7)  * 32;
    const int h0  = (blockIdx.x >> 3) * 32;
    const float* h_in  = g_h[par];
    float*       h_out = g_h[par^1];

    const int tr = tid >> 4;   // 0..15 -> rows 2tr,2tr+1
    const int cg = tid & 15;   // 0..15 -> cols cg*8..cg*8+7

    float acc[2][8];
    #pragma unroll
    for (int i=0;i<2;i++)
        #pragma unroll
        for (int j=0;j<8;j++) acc[i][j]=0.f;

    auto loadB4 = [&](int e4, int k0)->float4 {
        int crow = e4 >> 2;
        int k    = k0 + (e4 & 3)*4;
        int g = crow >> 5, j = crow & 31;
        int wrow = g*Hn + h0 + j;
        if (k < K1) return *(const float4*)(Wi + wrow*K1 + k);
        return *(const float4*)(Wh + wrow*Hn + (k - K1));
    };
    auto loadA4 = [&](int k0)->float4 {
        int r  = tid >> 2;
        int k  = k0 + (tid & 3)*4;
        int bg = b0 + r;
        if (k < K1){
            if (ENC){
                int vid = enc_input[bg*Sn + t];
                return *(const float4*)(enc_embed + vid*En + k);
            } else {
                if (k < EDn){
                    int a = g_inp[bg*2];
                    return *(const float4*)(act_emb + a*EDn + k);
                } else {
                    int tt = g_inp[bg*2+1];
                    return *(const float4*)(tgt_emb + tt*EDn + (k-EDn));
                }
            }
        }
        return *(const float4*)(h_in + bg*Hn + (k - K1));
    };

    // prefetch tile 0
    float4 bp0 = loadB4(tid, 0), bp1 = loadB4(tid+256, 0);
    float4 ap; if (tid < 128) ap = loadA4(0);

    for (int kt=0; kt<NKT; kt++){
        // store current tile into smem
        { int crow=tid>>2, kk=(tid&3)*4;
          Bs[kk][crow]=bp0.x; Bs[kk+1][crow]=bp0.y; Bs[kk+2][crow]=bp0.z; Bs[kk+3][crow]=bp0.w; }
        { int e=tid+256; int crow=e>>2, kk=(e&3)*4;
          Bs[kk][crow]=bp1.x; Bs[kk+1][crow]=bp1.y; Bs[kk+2][crow]=bp1.z; Bs[kk+3][crow]=bp1.w; }
        if (tid < 128){
            int r=tid>>2, kk=(tid&3)*4;
            As[kk][r]=ap.x; As[kk+1][r]=ap.y; As[kk+2][r]=ap.z; As[kk+3][r]=ap.w;
        }
        __syncthreads();

        // prefetch next tile (overlaps with compute below)
        if (kt+1 < NKT){
            int k0 = (kt+1)*16;
            bp0 = loadB4(tid, k0); bp1 = loadB4(tid+256, k0);
            if (tid < 128) ap = loadA4(k0);
        }

        #pragma unroll
        for (int kk=0; kk<16; kk++){
            float2 av  = *(const float2*)&As[kk][2*tr];
            float4 bv0 = *(const float4*)&Bs[kk][cg*8];
            float4 bv1 = *(const float4*)&Bs[kk][cg*8+4];
            acc[0][0] += av.x*bv0.x; acc[0][1] += av.x*bv0.y;
            acc[0][2] += av.x*bv0.z; acc[0][3] += av.x*bv0.w;
            acc[0][4] += av.x*bv1.x; acc[0][5] += av.x*bv1.y;
            acc[0][6] += av.x*bv1.z; acc[0][7] += av.x*bv1.w;
            acc[1][0] += av.y*bv0.x; acc[1][1] += av.y*bv0.y;
            acc[1][2] += av.y*bv0.z; acc[1][3] += av.y*bv0.w;
            acc[1][4] += av.y*bv1.x; acc[1][5] += av.y*bv1.y;
            acc[1][6] += av.y*bv1.z; acc[1][7] += av.y*bv1.w;
        }
        __syncthreads();
    }

    // spill z tile to smem, then do the gate math per (b,h) element
    #pragma unroll
    for (int ii=0; ii<2; ii++)
        #pragma unroll
        for (int u=0; u<8; u++)
            zs[(2*tr+ii)*128 + cg*8 + u] = acc[ii][u];
    __syncthreads();

    #pragma unroll
    for (int q=0; q<4; q++){
        int p = tid + q*256;           // 0..1023 -> (r,j)
        int r = p >> 5, j = p & 31;
        int bg = b0 + r, hg = h0 + j;
        float zi = zs[r*128 +       j] + bias[         hg];
        float zf = zs[r*128 + 32 +  j] + bias[Hn     + hg];
        float zg = zs[r*128 + 64 +  j] + bias[2*Hn   + hg];
        float zo = zs[r*128 + 96 +  j] + bias[3*Hn   + hg];
        float cold = g_c[bg*Hn + hg];
        float cn = sigmoidf_(zf)*cold + sigmoidf_(zi)*tanhf(zg);
        g_c[bg*Hn + hg] = cn;
        float hn = sigmoidf_(zo)*tanhf(cn);
        h_out[bg*Hn + hg] = hn;
        if (ENC) g_enc_out[((size_t)t*Bn + bg)*Hn + hg] = hn;
    }
}

// ---------------------------------------------------------------------------
// enc_score[s][b] = dot(enc_out[s,b,:], Wf[0:H]) ; one warp per (s,b)
// ---------------------------------------------------------------------------
__global__ void enc_score_k(const float* __restrict__ Wf){
    int w    = (blockIdx.x*blockDim.x + threadIdx.x) >> 5;
    int lane = threadIdx.x & 31;
    int s = w >> 8, b = w & 255;
    const float* row = g_enc_out + ((size_t)s*Bn + b)*Hn;
    float acc = 0.f;
    for (int h = lane; h < Hn; h += 32) acc += row[h]*Wf[h];
    #pragma unroll
    for (int o=16;o;o>>=1) acc += __shfl_down_sync(0xffffffffu, acc, o);
    if (lane==0) g_enc_score[s*Bn + b] = acc;
}

// ---------------------------------------------------------------------------
// Attention + output heads + argmax feedback. One block per batch row.
// ---------------------------------------------------------------------------
__global__ __launch_bounds__(256) void attn_k(
    const float* __restrict__ Wf, const float* __restrict__ bfv,
    const float* __restrict__ W_a, const float* __restrict__ b_a,
    const float* __restrict__ W_t, const float* __restrict__ b_t,
    float* __restrict__ out, int t, int par)
{
    __shared__ float sh_w[Sn];
    __shared__ float sh_ctx[Hn];
    __shared__ float red[256];
    __shared__ float sh_p[An+NTn];

    const int b = blockIdx.x, tid = threadIdx.x;
    const float* h = g_h[par] + b*Hn;

    // h . Wd (constant shift per b; kept for numerical fidelity with reference)
    float part = h[tid]*Wf[Hn+tid] + h[tid+256]*Wf[Hn+tid+256];
    red[tid] = part; __syncthreads();
    for (int o=128;o;o>>=1){ if (tid<o) red[tid]+=red[tid+o]; __syncthreads(); }
    float hdot = red[0] + bfv[0];
    __syncthreads();

    // softmax over s
    float sc = g_enc_score[tid*Bn + b] + hdot;
    red[tid] = sc; __syncthreads();
    for (int o=128;o;o>>=1){ if (tid<o) red[tid]=fmaxf(red[tid],red[tid+o]); __syncthreads(); }
    float m = red[0]; __syncthreads();
    float e = expf(sc - m);
    red[tid] = e; __syncthreads();
    for (int o=128;o;o>>=1){ if (tid<o) red[tid]+=red[tid+o]; __syncthreads(); }
    float inv = 1.f/red[0];
    __syncthreads();
    sh_w[tid] = e*inv;
    __syncthreads();

    // ctx[b,:] = sum_s w[s] * enc_out[s,b,:]
    float a0=0.f, a1=0.f;
    const float* base = g_enc_out + (size_t)b*Hn;
    for (int s=0; s<Sn; s++){
        float ws = sh_w[s];
        const float* row = base + (size_t)s*Bn*Hn;
        a0 += ws*row[tid]; a1 += ws*row[tid+256];
    }
    sh_ctx[tid]=a0; sh_ctx[tid+256]=a1;
    __syncthreads();

    // output heads
    if (tid < An){
        float acc = b_a[tid];
        const float* w = W_a + tid*Hn;
        #pragma unroll 8
        for (int k=0;k<Hn;k++) acc += sh_ctx[k]*w[k];
        sh_p[tid] = acc;
        out[(b*Tn + t)*An + tid] = acc;
    } else if (tid < An+NTn){
        int j = tid - An;
        float acc = b_t[j];
        const float* w = W_t + j*Hn;
        #pragma unroll 8
        for (int k=0;k<Hn;k++) acc += sh_ctx[k]*w[k];
        sh_p[tid] = acc;
        out[Bn*Tn*An + (b*Tn + t)*NTn + j] = acc;
    }
    __syncthreads();

    if (tid==0){
        int ia=0; float bv=sh_p[0];
        #pragma unroll
        for (int a=1;a<An;a++) if (sh_p[a]>bv){bv=sh_p[a]; ia=a;}
        int it=0; float tv=sh_p[An];
        for (int j=1;j<NTn;j++) if (sh_p[An+j]>tv){tv=sh_p[An+j]; it=j;}
        g_inp[b*2]   = ia;
        g_inp[b*2+1] = it;
    }
}

extern "C" void kernel_launch(void* const* d_in, const int* in_sizes, int n_in,
                              void* d_out, int out_size)
{
    const int*   enc_input = (const int*)  d_in[0];
    // d_in[1] = decoder_target (unused by reference)
    const float* enc_embed = (const float*)d_in[2];
    const float* Wi_e      = (const float*)d_in[3];
    const float* Wh_e      = (const float*)d_in[4];
    const float* b_e       = (const float*)d_in[5];
    const float* act_emb   = (const float*)d_in[6];
    const float* tgt_emb   = (const float*)d_in[7];
    const float* Wi_d      = (const float*)d_in[8];
    const float* Wh_d      = (const float*)d_in[9];
    const float* b_d       = (const float*)d_in[10];
    const float* W_a       = (const float*)d_in[11];
    const float* b_a       = (const float*)d_in[12];
    const float* W_t       = (const float*)d_in[13];
    const float* b_t       = (const float*)d_in[14];
    const float* Wf        = (const float*)d_in[15];
    const float* bf        = (const float*)d_in[16];
    float* out = (float*)d_out;

    init_k<<<(Bn*Hn + 255)/256, 256>>>();

    for (int t=0; t<Sn; t++)
        lstm_k<En, true><<<128, 256>>>(Wi_e, Wh_e, b_e,
                                       enc_input, enc_embed, nullptr, nullptr,
                                       t, t & 1);

    enc_score_k<<<(Sn*Bn)/8, 256>>>(Wf);

    for (int t=0; t<Tn; t++){
        lstm_k<2*EDn, false><<<128, 256>>>(Wi_d, Wh_d, b_d,
                                           nullptr, nullptr, act_emb, tgt_emb,
                                           t, t & 1);
        attn_k<<<Bn, 256>>>(Wf, bf, W_a, b_a, W_t, b_t, out, t, (t & 1) ^ 1);
    }
}